// round 2
// baseline (speedup 1.0000x reference)
#include <cuda_runtime.h>

// DiffOmegaVectorNorm: masked vorticity-difference L2 norm -> scalar.
//
// Identities:
//   omega(P)-omega(T) = omega(P-T)            (linearity: one curl, not two)
//   scale/(2*delta) = 10/10 = 1               (coefficient-free stencil)
//   active(voxel) = AND of 27 mask neighbors  (b*(1-near_wall) gate)
//   num_grids = #active interior voxels
//
// Two-pass: pass A packs mask -> bitmask rows with x-direction 3-AND folded in
// (33.5MB float -> 4MB bits, read once). Main kernel builds the 27-AND from 9
// neighbor rows of packed bits, then runs the gated 24-load stencil.
//
// Shapes: P,T (2,4,64,256,256) f32; M (2,1,64,256,256) f32. Output: 1 f32.

#define TZ 4
#define TY 8
#define NROWS (2 * 64 * 256)

__device__ double g_sum;
__device__ unsigned long long g_cnt;
__device__ unsigned int g_xmin[NROWS * 8];   // per-row 256-bit x-3AND mask

// ---- Pass A: pack mask rows to bits, fold in x-direction 3-wide AND ----
__global__ __launch_bounds__(256) void dovn_mask_kernel(const float* __restrict__ M) {
    if (blockIdx.x == 0 && threadIdx.x == 0) { g_sum = 0.0; g_cnt = 0ull; }

    const int warp = threadIdx.x >> 5;
    const int lane = threadIdx.x & 31;
    const int row  = blockIdx.x * 8 + warp;          // (b,z,y) row index
    const float* mrow = M + (size_t)row * 256;

    unsigned w0, w1, w2, w3, w4, w5, w6, w7;
    w0 = __ballot_sync(0xFFFFFFFFu, mrow[  0 + lane] > 0.5f);
    w1 = __ballot_sync(0xFFFFFFFFu, mrow[ 32 + lane] > 0.5f);
    w2 = __ballot_sync(0xFFFFFFFFu, mrow[ 64 + lane] > 0.5f);
    w3 = __ballot_sync(0xFFFFFFFFu, mrow[ 96 + lane] > 0.5f);
    w4 = __ballot_sync(0xFFFFFFFFu, mrow[128 + lane] > 0.5f);
    w5 = __ballot_sync(0xFFFFFFFFu, mrow[160 + lane] > 0.5f);
    w6 = __ballot_sync(0xFFFFFFFFu, mrow[192 + lane] > 0.5f);
    w7 = __ballot_sync(0xFFFFFFFFu, mrow[224 + lane] > 0.5f);

    // x-direction 3-AND: bit k -> bits k-1 & k & k+1 (cross-word carries)
    unsigned out = 0;
    #define XMIN(J, WL, WC, WH) { \
        unsigned xm = (WC) & (((WC) << 1) | ((WL) >> 31)) & (((WC) >> 1) | ((WH) << 31)); \
        if (lane == (J)) out = xm; }
    XMIN(0, 0u, w0, w1); XMIN(1, w0, w1, w2); XMIN(2, w1, w2, w3); XMIN(3, w2, w3, w4);
    XMIN(4, w3, w4, w5); XMIN(5, w4, w5, w6); XMIN(6, w5, w6, w7); XMIN(7, w6, w7, 0u);
    #undef XMIN

    if (lane < 8) g_xmin[row * 8 + lane] = out;
}

// ---- finalize ----
__global__ void dovn_final_kernel(float* out) {
    out[0] = (float)(g_sum / (double)g_cnt);
}

// ---- Main: 27-AND from packed bits + gated vorticity-diff stencil ----
__global__ __launch_bounds__(256) void dovn_main_kernel(
    const float* __restrict__ P,
    const float* __restrict__ T)
{
    __shared__ unsigned int sxm[TZ + 2][TY + 2][8];  // x-3AND bits, tile + halo
    __shared__ unsigned int act[TZ][TY][8];          // final active bits
    __shared__ float wsum[8];
    __shared__ int   wcnt[8];

    const int x    = threadIdx.x;          // x coordinate 0..255
    const int warp = x >> 5;
    const int lane = x & 31;
    const int y0   = 1 + blockIdx.x * TY;
    const int z0   = 1 + blockIdx.y * TZ;
    const int b    = blockIdx.z;

    // 1. Load packed-bit halo (60 rows x 8 words = 480 words)
    for (int idx = x; idx < (TZ + 2) * (TY + 2) * 8; idx += 256) {
        const int zz = idx / ((TY + 2) * 8);
        const int r  = idx % ((TY + 2) * 8);
        const int yy = r >> 3;
        const int j  = r & 7;
        const int gz = z0 - 1 + zz;
        const int gy = y0 - 1 + yy;
        unsigned v = 0u;
        if (gz < 64 && gy < 256)
            v = g_xmin[(((b * 64 + gz) * 256 + gy) << 3) + j];
        sxm[zz][yy][j] = v;
    }
    __syncthreads();

    // 2. 3x3 AND in (z,y) + interior bounds -> active bits (256 words, 1/thread)
    {
        const int zz = x >> 6;
        const int yy = (x >> 3) & 7;
        const int j  = x & 7;
        unsigned a = sxm[zz][yy][j];
        a &= sxm[zz][yy + 1][j];  a &= sxm[zz][yy + 2][j];
        a &= sxm[zz + 1][yy][j];  a &= sxm[zz + 1][yy + 1][j];  a &= sxm[zz + 1][yy + 2][j];
        a &= sxm[zz + 2][yy][j];  a &= sxm[zz + 2][yy + 1][j];  a &= sxm[zz + 2][yy + 2][j];
        if (j == 0) a &= 0xFFFFFFFEu;   // x >= 1
        if (j == 7) a &= 0x7FFFFFFFu;   // x <= 254
        if (z0 + zz > 62)  a = 0u;      // z interior
        if (y0 + yy > 254) a = 0u;      // y interior
        act[zz][yy][j] = a;
    }
    __syncthreads();

    // 3. Gated vorticity-diff stencil
    float lsum = 0.0f;
    int   lcnt = 0;
    const int      wj  = x >> 5;
    const unsigned bit = 1u << lane;
    const unsigned cb  = (unsigned)b * 4u * 64u * 65536u;
    const unsigned CS  = 64u * 65536u;
    const unsigned SZ  = 65536u;
    const unsigned SY  = 256u;

    #pragma unroll
    for (int zz = 0; zz < TZ; ++zz) {
        #pragma unroll
        for (int yy = 0; yy < TY; ++yy) {
            const unsigned w = act[zz][yy][wj];
            if (w == 0u) continue;           // warp-uniform skip
            if (w & bit) {
                const unsigned gz = (unsigned)(z0 + zz);
                const unsigned gy = (unsigned)(y0 + yy);
                const unsigned o1 = cb + CS + gz * SZ + gy * SY + (unsigned)x; // u
                const unsigned o2 = o1 + CS;                                   // v
                const unsigned o3 = o2 + CS;                                   // w

                const float u_zp = P[o1 + SZ] - T[o1 + SZ];
                const float u_zm = P[o1 - SZ] - T[o1 - SZ];
                const float u_yp = P[o1 + SY] - T[o1 + SY];
                const float u_ym = P[o1 - SY] - T[o1 - SY];
                const float v_zp = P[o2 + SZ] - T[o2 + SZ];
                const float v_zm = P[o2 - SZ] - T[o2 - SZ];
                const float v_xp = P[o2 + 1u] - T[o2 + 1u];
                const float v_xm = P[o2 - 1u] - T[o2 - 1u];
                const float w_yp = P[o3 + SY] - T[o3 + SY];
                const float w_ym = P[o3 - SY] - T[o3 - SY];
                const float w_xp = P[o3 + 1u] - T[o3 + 1u];
                const float w_xm = P[o3 - 1u] - T[o3 - 1u];

                const float vx = (w_yp - w_ym) - (v_zp - v_zm);
                const float vy = (u_zp - u_zm) - (w_xp - w_xm);
                const float vz = (v_xp - v_xm) - (u_yp - u_ym);

                lsum += sqrtf(vx * vx + vy * vy + vz * vz);
                lcnt++;
            }
        }
    }

    // 4. Block reduction + global atomics
    #pragma unroll
    for (int off = 16; off; off >>= 1) {
        lsum += __shfl_down_sync(0xFFFFFFFFu, lsum, off);
        lcnt += __shfl_down_sync(0xFFFFFFFFu, lcnt, off);
    }
    if (lane == 0) { wsum[warp] = lsum; wcnt[warp] = lcnt; }
    __syncthreads();
    if (x == 0) {
        float s = 0.0f;
        int   c = 0;
        #pragma unroll
        for (int i = 0; i < 8; ++i) { s += wsum[i]; c += wcnt[i]; }
        if (c > 0) {
            atomicAdd(&g_sum, (double)s);
            atomicAdd(&g_cnt, (unsigned long long)c);
        }
    }
}

extern "C" void kernel_launch(void* const* d_in, const int* in_sizes, int n_in,
                              void* d_out, int out_size) {
    const float* P = (const float*)d_in[0];
    const float* T = (const float*)d_in[1];
    const float* M = (const float*)d_in[2];

    dovn_mask_kernel<<<NROWS / 8, 256>>>(M);     // also zeroes accumulators
    dim3 grid(32, 16, 2);
    dovn_main_kernel<<<grid, 256>>>(P, T);
    dovn_final_kernel<<<1, 1>>>((float*)d_out);
}

// round 3
// speedup vs baseline: 1.9283x; 1.9283x over previous
#include <cuda_runtime.h>

// DiffOmegaVectorNorm: masked vorticity-difference L2 norm -> scalar.
//
// Identities:
//   omega(P)-omega(T) = omega(P-T)            (one curl on the difference)
//   scale/(2*delta) = 10/10 = 1               (coefficient-free stencil)
//   active(voxel) = AND of 27 mask neighbors  (b*(1-near_wall) gate)
//   num_grids = #active interior voxels
//
// Pass A: vectorized mask pack -> per-row 256-bit masks with x-direction 3-AND
// folded in (pure register/shuffle, 2xLDG.128 per thread).
// Main: 27-AND from packed bits, block-wide COMPACTION of active voxels into a
// shared worklist, then a fully-occupied gather stencil over active voxels only.
//
// Shapes: P,T (2,4,64,256,256) f32; M (2,1,64,256,256) f32. Output: 1 f32.

#define TZ 4
#define TY 8
#define NROWS (2 * 64 * 256)

__device__ double g_sum;
__device__ unsigned long long g_cnt;
__device__ unsigned int g_xmin[NROWS * 8];   // per-row 256-bit x-3AND mask

// ---- Pass A: pack mask rows to bits with x-3AND, one warp per row ----
__global__ __launch_bounds__(256) void dovn_mask_kernel(const float* __restrict__ M) {
    if (blockIdx.x == 0 && threadIdx.x == 0) { g_sum = 0.0; g_cnt = 0ull; }

    const int warp = threadIdx.x >> 5;
    const int lane = threadIdx.x & 31;
    const int row  = blockIdx.x * 8 + warp;           // (b,z,y) row
    const float* mp = M + (size_t)row * 256 + lane * 8;

    const float4 a = *(const float4*)mp;
    const float4 c = *(const float4*)(mp + 4);
    unsigned byte = 0;
    byte |= (a.x > 0.5f) ? 1u : 0u;   byte |= (a.y > 0.5f) ? 2u : 0u;
    byte |= (a.z > 0.5f) ? 4u : 0u;   byte |= (a.w > 0.5f) ? 8u : 0u;
    byte |= (c.x > 0.5f) ? 16u : 0u;  byte |= (c.y > 0.5f) ? 32u : 0u;
    byte |= (c.z > 0.5f) ? 64u : 0u;  byte |= (c.w > 0.5f) ? 128u : 0u;

    // assemble 32-bit word j = lane/4 from bytes of lanes 4j..4j+3
    const int g = lane & ~3;
    const int j = lane >> 2;
    unsigned w = __shfl_sync(0xFFFFFFFFu, byte, g)
               | (__shfl_sync(0xFFFFFFFFu, byte, g + 1) << 8)
               | (__shfl_sync(0xFFFFFFFFu, byte, g + 2) << 16)
               | (__shfl_sync(0xFFFFFFFFu, byte, g + 3) << 24);

    unsigned wl = __shfl_sync(0xFFFFFFFFu, w, (lane >= 4) ? lane - 4 : lane);
    unsigned wh = __shfl_sync(0xFFFFFFFFu, w, (lane < 28) ? lane + 4 : lane);
    if (j == 0) wl = 0u;
    if (j == 7) wh = 0u;

    const unsigned xm = w & ((w << 1) | (wl >> 31)) & ((w >> 1) | (wh << 31));
    if ((lane & 3) == 0) g_xmin[row * 8 + j] = xm;
}

// ---- finalize ----
__global__ void dovn_final_kernel(float* out) {
    out[0] = (float)(g_sum / (double)g_cnt);
}

// ---- Main: 27-AND + compaction + gather stencil ----
__global__ __launch_bounds__(256) void dovn_main_kernel(
    const float* __restrict__ P,
    const float* __restrict__ T)
{
    __shared__ unsigned int   sxm[TZ + 2][TY + 2][8];  // packed halo bits
    __shared__ unsigned short list[TZ * TY * 256];     // worst-case worklist (16KB)
    __shared__ int  wtot[8], woff[9];
    __shared__ float wsum[8];

    const int x    = threadIdx.x;     // also linear word id (zz,yy,j)
    const int warp = x >> 5;
    const int lane = x & 31;
    const int y0   = 1 + blockIdx.x * TY;
    const int z0   = 1 + blockIdx.y * TZ;
    const int b    = blockIdx.z;

    // 1. Load packed-bit halo (60 rows x 8 words)
    for (int idx = x; idx < (TZ + 2) * (TY + 2) * 8; idx += 256) {
        const int zz = idx / ((TY + 2) * 8);
        const int r  = idx % ((TY + 2) * 8);
        const int yy = r >> 3;
        const int j  = r & 7;
        const int gz = z0 - 1 + zz;
        const int gy = y0 - 1 + yy;
        unsigned v = 0u;
        if (gz < 64 && gy < 256)
            v = g_xmin[(((b * 64 + gz) * 256 + gy) << 3) + j];
        sxm[zz][yy][j] = v;
    }
    __syncthreads();

    // 2. 3x3 (z,y) AND + interior bounds -> one active word per thread
    unsigned a;
    const int zz = x >> 6;
    const int yy = (x >> 3) & 7;
    const int j  = x & 7;
    {
        a  = sxm[zz][yy][j];
        a &= sxm[zz][yy + 1][j];  a &= sxm[zz][yy + 2][j];
        a &= sxm[zz + 1][yy][j];  a &= sxm[zz + 1][yy + 1][j];  a &= sxm[zz + 1][yy + 2][j];
        a &= sxm[zz + 2][yy][j];  a &= sxm[zz + 2][yy + 1][j];  a &= sxm[zz + 2][yy + 2][j];
        if (j == 0) a &= 0xFFFFFFFEu;   // x >= 1
        if (j == 7) a &= 0x7FFFFFFFu;   // x <= 254
        if (z0 + zz > 62)  a = 0u;
        if (y0 + yy > 254) a = 0u;
    }

    // 3. Block-wide exclusive scan of popcounts -> compact worklist
    const int c = __popc(a);
    int s = c;
    #pragma unroll
    for (int off = 1; off < 32; off <<= 1) {
        const int n = __shfl_up_sync(0xFFFFFFFFu, s, off);
        if (lane >= off) s += n;
    }
    if (lane == 31) wtot[warp] = s;
    __syncthreads();
    if (x == 0) {
        int acc = 0;
        #pragma unroll
        for (int i = 0; i < 8; ++i) { woff[i] = acc; acc += wtot[i]; }
        woff[8] = acc;
    }
    __syncthreads();
    const int total = woff[8];
    {
        int o = woff[warp] + s - c;
        unsigned w = a;
        const unsigned hdr = ((unsigned)zz << 11) | ((unsigned)yy << 8) | ((unsigned)j << 5);
        while (w) {
            const int bit = __ffs(w) - 1;
            w &= w - 1;
            list[o++] = (unsigned short)(hdr | (unsigned)bit);
        }
    }
    __syncthreads();

    // 4. Gather stencil over active voxels, all lanes busy
    float lsum = 0.0f;
    const unsigned cb = (unsigned)b * 4u * 64u * 65536u;
    const unsigned CS = 64u * 65536u;
    const unsigned SZ = 65536u;
    const unsigned SY = 256u;

    for (int i = x; i < total; i += 256) {
        const unsigned e  = list[i];
        const unsigned xx = e & 255u;
        const unsigned ey = (e >> 8) & 7u;
        const unsigned ez = e >> 11;
        const unsigned gz = (unsigned)z0 + ez;
        const unsigned gy = (unsigned)y0 + ey;
        const unsigned o1 = cb + CS + gz * SZ + gy * SY + xx;  // u
        const unsigned o2 = o1 + CS;                           // v
        const unsigned o3 = o2 + CS;                           // w

        const float u_zp = __ldg(P + o1 + SZ) - __ldg(T + o1 + SZ);
        const float u_zm = __ldg(P + o1 - SZ) - __ldg(T + o1 - SZ);
        const float u_yp = __ldg(P + o1 + SY) - __ldg(T + o1 + SY);
        const float u_ym = __ldg(P + o1 - SY) - __ldg(T + o1 - SY);
        const float v_zp = __ldg(P + o2 + SZ) - __ldg(T + o2 + SZ);
        const float v_zm = __ldg(P + o2 - SZ) - __ldg(T + o2 - SZ);
        const float v_xp = __ldg(P + o2 + 1u) - __ldg(T + o2 + 1u);
        const float v_xm = __ldg(P + o2 - 1u) - __ldg(T + o2 - 1u);
        const float w_yp = __ldg(P + o3 + SY) - __ldg(T + o3 + SY);
        const float w_ym = __ldg(P + o3 - SY) - __ldg(T + o3 - SY);
        const float w_xp = __ldg(P + o3 + 1u) - __ldg(T + o3 + 1u);
        const float w_xm = __ldg(P + o3 - 1u) - __ldg(T + o3 - 1u);

        const float vx = (w_yp - w_ym) - (v_zp - v_zm);
        const float vy = (u_zp - u_zm) - (w_xp - w_xm);
        const float vz = (v_xp - v_xm) - (u_yp - u_ym);

        lsum += sqrtf(vx * vx + vy * vy + vz * vz);
    }

    // 5. Reduce sum; count is simply `total` per block
    #pragma unroll
    for (int off = 16; off; off >>= 1)
        lsum += __shfl_down_sync(0xFFFFFFFFu, lsum, off);
    if (lane == 0) wsum[warp] = lsum;
    __syncthreads();
    if (x == 0) {
        float ssum = 0.0f;
        #pragma unroll
        for (int i = 0; i < 8; ++i) ssum += wsum[i];
        if (total > 0) {
            atomicAdd(&g_sum, (double)ssum);
            atomicAdd(&g_cnt, (unsigned long long)total);
        }
    }
}

extern "C" void kernel_launch(void* const* d_in, const int* in_sizes, int n_in,
                              void* d_out, int out_size) {
    const float* P = (const float*)d_in[0];
    const float* T = (const float*)d_in[1];
    const float* M = (const float*)d_in[2];

    dovn_mask_kernel<<<NROWS / 8, 256>>>(M);     // packs mask + zeroes accumulators
    dim3 grid(32, 16, 2);
    dovn_main_kernel<<<grid, 256>>>(P, T);
    dovn_final_kernel<<<1, 1>>>((float*)d_out);
}

// round 4
// speedup vs baseline: 2.0986x; 1.0883x over previous
#include <cuda_runtime.h>

// DiffOmegaVectorNorm: masked vorticity-difference L2 norm -> scalar.
// SINGLE fused kernel (mask pack + 27-AND + compaction + gather + finalize).
//
// Identities:
//   omega(P)-omega(T) = omega(P-T)            (one curl on the difference)
//   scale/(2*delta) = 10/10 = 1               (coefficient-free stencil)
//   active(voxel) = AND of 27 mask neighbors  (b*(1-near_wall) gate)
//   num_grids = #active interior voxels
//
// Shapes: P,T (2,4,64,256,256) f32; M (2,1,64,256,256) f32. Output: 1 f32.

#define TZ 4
#define TY 8
#define NBLK (32 * 16 * 2)

__device__ double       g_part[NBLK];   // per-block partial sums (overwritten each call)
__device__ int          g_pcnt[NBLK];   // per-block active counts
__device__ unsigned int g_ctr = 0;      // completion ticket (reset by last block)

__global__ __launch_bounds__(256) void dovn_fused_kernel(
    const float* __restrict__ P,
    const float* __restrict__ T,
    const float* __restrict__ M,
    float* __restrict__ out)
{
    __shared__ unsigned int   sxm[TZ + 2][TY + 2][8];  // packed x-3AND bits, tile+halo
    __shared__ unsigned short list[TZ * TY * 256];     // worklist (16KB worst case)
    __shared__ int  wtot[8], woff[9];
    __shared__ float wsum[8];
    __shared__ int  sIsLast;

    const int x    = threadIdx.x;
    const int warp = x >> 5;
    const int lane = x & 31;
    const int y0   = 1 + blockIdx.x * TY;
    const int z0   = 1 + blockIdx.y * TZ;
    const int b    = blockIdx.z;
    const int bid  = blockIdx.x + 32 * (blockIdx.y + 16 * blockIdx.z);

    // ---- 1. Pack mask halo rows -> bits with x-direction 3-AND (1 warp/row) ----
    for (int row = warp; row < (TZ + 2) * (TY + 2); row += 8) {
        const int zz = row / (TY + 2);
        const int yy = row % (TY + 2);
        const int gz = z0 - 1 + zz;
        const int gy = y0 - 1 + yy;
        unsigned xm = 0u;
        if (gz < 64 && gy < 256) {                     // warp-uniform branch
            const float* mp = M + ((((size_t)b * 64 + gz) << 8 | gy) << 8) + lane * 8;
            const float4 fa = *(const float4*)mp;
            const float4 fc = *(const float4*)(mp + 4);
            unsigned byte = 0;
            byte |= (fa.x > 0.5f) ? 1u : 0u;   byte |= (fa.y > 0.5f) ? 2u : 0u;
            byte |= (fa.z > 0.5f) ? 4u : 0u;   byte |= (fa.w > 0.5f) ? 8u : 0u;
            byte |= (fc.x > 0.5f) ? 16u : 0u;  byte |= (fc.y > 0.5f) ? 32u : 0u;
            byte |= (fc.z > 0.5f) ? 64u : 0u;  byte |= (fc.w > 0.5f) ? 128u : 0u;
            // assemble word j = lane/4 from bytes of lanes 4j..4j+3
            const int g = lane & ~3;
            unsigned w = __shfl_sync(0xFFFFFFFFu, byte, g)
                       | (__shfl_sync(0xFFFFFFFFu, byte, g + 1) << 8)
                       | (__shfl_sync(0xFFFFFFFFu, byte, g + 2) << 16)
                       | (__shfl_sync(0xFFFFFFFFu, byte, g + 3) << 24);
            const int jw = lane >> 2;
            unsigned wl = __shfl_sync(0xFFFFFFFFu, w, (lane >= 4) ? lane - 4 : lane);
            unsigned wh = __shfl_sync(0xFFFFFFFFu, w, (lane < 28) ? lane + 4 : lane);
            if (jw == 0) wl = 0u;
            if (jw == 7) wh = 0u;
            xm = w & ((w << 1) | (wl >> 31)) & ((w >> 1) | (wh << 31));
        }
        if ((lane & 3) == 0) sxm[zz][yy][lane >> 2] = xm;
    }
    __syncthreads();

    // ---- 2. 3x3 (z,y) AND + interior bounds -> one active word per thread ----
    unsigned a;
    const int zz = x >> 6;
    const int yy = (x >> 3) & 7;
    const int j  = x & 7;
    {
        a  = sxm[zz][yy][j];
        a &= sxm[zz][yy + 1][j];  a &= sxm[zz][yy + 2][j];
        a &= sxm[zz + 1][yy][j];  a &= sxm[zz + 1][yy + 1][j];  a &= sxm[zz + 1][yy + 2][j];
        a &= sxm[zz + 2][yy][j];  a &= sxm[zz + 2][yy + 1][j];  a &= sxm[zz + 2][yy + 2][j];
        if (j == 0) a &= 0xFFFFFFFEu;   // x >= 1
        if (j == 7) a &= 0x7FFFFFFFu;   // x <= 254
        if (z0 + zz > 62)  a = 0u;
        if (y0 + yy > 254) a = 0u;
    }

    // ---- 3. Block-wide scan -> compact worklist ----
    const int c = __popc(a);
    int s = c;
    #pragma unroll
    for (int off = 1; off < 32; off <<= 1) {
        const int n = __shfl_up_sync(0xFFFFFFFFu, s, off);
        if (lane >= off) s += n;
    }
    if (lane == 31) wtot[warp] = s;
    __syncthreads();
    if (x == 0) {
        int acc = 0;
        #pragma unroll
        for (int i = 0; i < 8; ++i) { woff[i] = acc; acc += wtot[i]; }
        woff[8] = acc;
    }
    __syncthreads();
    const int total = woff[8];
    {
        int o = woff[warp] + s - c;
        unsigned w = a;
        const unsigned hdr = ((unsigned)zz << 11) | ((unsigned)yy << 8) | ((unsigned)j << 5);
        while (w) {
            const int bit = __ffs(w) - 1;
            w &= w - 1;
            list[o++] = (unsigned short)(hdr | (unsigned)bit);
        }
    }
    __syncthreads();

    // ---- 4. Gather stencil over active voxels (all lanes busy) ----
    float lsum = 0.0f;
    const unsigned cb = (unsigned)b * 4u * 64u * 65536u;
    const unsigned CS = 64u * 65536u;
    const unsigned SZ = 65536u;
    const unsigned SY = 256u;

    for (int i = x; i < total; i += 256) {
        const unsigned e  = list[i];
        const unsigned xx = e & 255u;
        const unsigned ey = (e >> 8) & 7u;
        const unsigned ez = e >> 11;
        const unsigned o1 = cb + CS + ((unsigned)z0 + ez) * SZ + ((unsigned)y0 + ey) * SY + xx;
        const unsigned o2 = o1 + CS;
        const unsigned o3 = o2 + CS;

        const float u_zp = __ldg(P + o1 + SZ) - __ldg(T + o1 + SZ);
        const float u_zm = __ldg(P + o1 - SZ) - __ldg(T + o1 - SZ);
        const float u_yp = __ldg(P + o1 + SY) - __ldg(T + o1 + SY);
        const float u_ym = __ldg(P + o1 - SY) - __ldg(T + o1 - SY);
        const float v_zp = __ldg(P + o2 + SZ) - __ldg(T + o2 + SZ);
        const float v_zm = __ldg(P + o2 - SZ) - __ldg(T + o2 - SZ);
        const float v_xp = __ldg(P + o2 + 1u) - __ldg(T + o2 + 1u);
        const float v_xm = __ldg(P + o2 - 1u) - __ldg(T + o2 - 1u);
        const float w_yp = __ldg(P + o3 + SY) - __ldg(T + o3 + SY);
        const float w_ym = __ldg(P + o3 - SY) - __ldg(T + o3 - SY);
        const float w_xp = __ldg(P + o3 + 1u) - __ldg(T + o3 + 1u);
        const float w_xm = __ldg(P + o3 - 1u) - __ldg(T + o3 - 1u);

        const float vx = (w_yp - w_ym) - (v_zp - v_zm);
        const float vy = (u_zp - u_zm) - (w_xp - w_xm);
        const float vz = (v_xp - v_xm) - (u_yp - u_ym);

        lsum += sqrtf(vx * vx + vy * vy + vz * vz);
    }

    // ---- 5. Block reduce -> per-block partial slot ----
    #pragma unroll
    for (int off = 16; off; off >>= 1)
        lsum += __shfl_down_sync(0xFFFFFFFFu, lsum, off);
    if (lane == 0) wsum[warp] = lsum;
    __syncthreads();
    if (x == 0) {
        float ssum = 0.0f;
        #pragma unroll
        for (int i = 0; i < 8; ++i) ssum += wsum[i];
        g_part[bid] = (double)ssum;
        g_pcnt[bid] = total;
        __threadfence();
        const unsigned ticket = atomicAdd(&g_ctr, 1u);
        sIsLast = (ticket == NBLK - 1) ? 1 : 0;
    }
    __syncthreads();

    // ---- 6. Last block finalizes (and resets the ticket counter) ----
    if (sIsLast) {
        double ds = 0.0;
        long long dc = 0;
        for (int i = x; i < NBLK; i += 256) {
            ds += g_part[i];
            dc += (long long)g_pcnt[i];
        }
        #pragma unroll
        for (int off = 16; off; off >>= 1) {
            ds += __shfl_down_sync(0xFFFFFFFFu, ds, off);
            dc += __shfl_down_sync(0xFFFFFFFFu, dc, off);
        }
        __shared__ double fsum[8];
        __shared__ long long fcnt[8];
        if (lane == 0) { fsum[warp] = ds; fcnt[warp] = dc; }
        __syncthreads();
        if (x == 0) {
            double S = 0.0;
            long long C = 0;
            #pragma unroll
            for (int i = 0; i < 8; ++i) { S += fsum[i]; C += fcnt[i]; }
            out[0] = (float)(S / (double)C);
            g_ctr = 0u;   // re-arm for next graph replay
        }
    }
}

extern "C" void kernel_launch(void* const* d_in, const int* in_sizes, int n_in,
                              void* d_out, int out_size) {
    const float* P = (const float*)d_in[0];
    const float* T = (const float*)d_in[1];
    const float* M = (const float*)d_in[2];

    dim3 grid(32, 16, 2);
    dovn_fused_kernel<<<grid, 256>>>(P, T, M, (float*)d_out);
}

// round 12
// speedup vs baseline: 2.1261x; 1.0131x over previous
#include <cuda_runtime.h>

// DiffOmegaVectorNorm: masked vorticity-difference L2 norm -> scalar.
// Single fused kernel (mask pack + 27-AND + compaction + gather + finalize).
//
// Identities:
//   omega(P)-omega(T) = omega(P-T)            (one curl on the difference)
//   scale/(2*delta) = 10/10 = 1               (coefficient-free stencil)
//   active(voxel) = AND of 27 mask neighbors  (b*(1-near_wall) gate)
//   num_grids = #active interior voxels
//
// Tile: 8z x 8y x 256x, 512 threads (16 warps), 512 blocks -> ~86% warp-slot fill.
// Shapes: P,T (2,4,64,256,256) f32; M (2,1,64,256,256) f32. Output: 1 f32.

#define TZ 8
#define TY 8
#define NT 512
#define NW 16
#define NBLK (32 * 8 * 2)

__device__ double       g_part[NBLK];
__device__ int          g_pcnt[NBLK];
__device__ unsigned int g_ctr = 0;

__global__ __launch_bounds__(NT) void dovn_fused_kernel(
    const float* __restrict__ P,
    const float* __restrict__ T,
    const float* __restrict__ M,
    float* __restrict__ out)
{
    __shared__ unsigned int   sxm[TZ + 2][TY + 2][8];  // packed x-3AND bits, tile+halo
    __shared__ unsigned short list[TZ * TY * 256];     // worklist (32KB worst case)
    __shared__ int  wtot[NW], woff[NW + 1];
    __shared__ float wsum[NW];
    __shared__ int  sIsLast;

    const int x    = threadIdx.x;
    const int warp = x >> 5;
    const int lane = x & 31;
    const int y0   = 1 + blockIdx.x * TY;
    const int z0   = 1 + blockIdx.y * TZ;
    const int b    = blockIdx.z;
    const int bid  = blockIdx.x + 32 * (blockIdx.y + 8 * blockIdx.z);

    // ---- 1. Pack mask halo rows -> bits with x-direction 3-AND (1 warp/row) ----
    for (int row = warp; row < (TZ + 2) * (TY + 2); row += NW) {
        const int zz = row / (TY + 2);
        const int yy = row % (TY + 2);
        const int gz = z0 - 1 + zz;
        const int gy = y0 - 1 + yy;
        unsigned xm = 0u;
        if (gz < 64 && gy < 256) {                     // warp-uniform branch
            const float* mp = M + ((((size_t)b * 64 + gz) << 8 | gy) << 8) + lane * 8;
            const float4 fa = *(const float4*)mp;
            const float4 fc = *(const float4*)(mp + 4);
            unsigned byte = 0;
            byte |= (fa.x > 0.5f) ? 1u : 0u;   byte |= (fa.y > 0.5f) ? 2u : 0u;
            byte |= (fa.z > 0.5f) ? 4u : 0u;   byte |= (fa.w > 0.5f) ? 8u : 0u;
            byte |= (fc.x > 0.5f) ? 16u : 0u;  byte |= (fc.y > 0.5f) ? 32u : 0u;
            byte |= (fc.z > 0.5f) ? 64u : 0u;  byte |= (fc.w > 0.5f) ? 128u : 0u;
            const int g = lane & ~3;
            unsigned w = __shfl_sync(0xFFFFFFFFu, byte, g)
                       | (__shfl_sync(0xFFFFFFFFu, byte, g + 1) << 8)
                       | (__shfl_sync(0xFFFFFFFFu, byte, g + 2) << 16)
                       | (__shfl_sync(0xFFFFFFFFu, byte, g + 3) << 24);
            const int jw = lane >> 2;
            unsigned wl = __shfl_sync(0xFFFFFFFFu, w, (lane >= 4) ? lane - 4 : lane);
            unsigned wh = __shfl_sync(0xFFFFFFFFu, w, (lane < 28) ? lane + 4 : lane);
            if (jw == 0) wl = 0u;
            if (jw == 7) wh = 0u;
            xm = w & ((w << 1) | (wl >> 31)) & ((w >> 1) | (wh << 31));
        }
        if ((lane & 3) == 0) sxm[zz][yy][lane >> 2] = xm;
    }
    __syncthreads();

    // ---- 2. 27-AND: 512 words, exactly one per thread ----
    unsigned a;
    {
        const int zz = x >> 6;          // 0..7
        const int yy = (x >> 3) & 7;    // 0..7
        const int j  = x & 7;           // 0..7
        a  = sxm[zz][yy][j];
        a &= sxm[zz][yy + 1][j];  a &= sxm[zz][yy + 2][j];
        a &= sxm[zz + 1][yy][j];  a &= sxm[zz + 1][yy + 1][j];  a &= sxm[zz + 1][yy + 2][j];
        a &= sxm[zz + 2][yy][j];  a &= sxm[zz + 2][yy + 1][j];  a &= sxm[zz + 2][yy + 2][j];
        if (j == 0) a &= 0xFFFFFFFEu;   // x >= 1
        if (j == 7) a &= 0x7FFFFFFFu;   // x <= 254
        if (z0 + zz > 62)  a = 0u;      // interior z
        if (y0 + yy > 254) a = 0u;      // interior y
    }

    // ---- 3. Block-wide scan -> compact worklist (single round) ----
    const int c = __popc(a);
    int s = c;
    #pragma unroll
    for (int off = 1; off < 32; off <<= 1) {
        const int n = __shfl_up_sync(0xFFFFFFFFu, s, off);
        if (lane >= off) s += n;
    }
    if (lane == 31) wtot[warp] = s;
    __syncthreads();
    if (x == 0) {
        int acc = 0;
        #pragma unroll
        for (int i = 0; i < NW; ++i) { woff[i] = acc; acc += wtot[i]; }
        woff[NW] = acc;
    }
    __syncthreads();
    const int total = woff[NW];
    {
        int o = woff[warp] + s - c;
        unsigned w = a;
        const unsigned hdr = (unsigned)x << 5;   // (zz,yy,j) header = word id * 32
        while (w) {
            const int bit = __ffs(w) - 1;
            w &= w - 1;
            list[o++] = (unsigned short)(hdr | (unsigned)bit);
        }
    }
    __syncthreads();

    // ---- 4. Gather stencil over active voxels (all lanes busy) ----
    float lsum = 0.0f;
    const unsigned cb = (unsigned)b * 4u * 64u * 65536u;
    const unsigned CS = 64u * 65536u;
    const unsigned SZ = 65536u;
    const unsigned SY = 256u;

    for (int i = x; i < total; i += NT) {
        const unsigned e  = list[i];
        const unsigned xx = e & 255u;            // j*32 + bit
        const unsigned ey = (e >> 8) & 7u;
        const unsigned ez = e >> 11;
        const unsigned o1 = cb + CS + ((unsigned)z0 + ez) * SZ + ((unsigned)y0 + ey) * SY + xx;
        const unsigned o2 = o1 + CS;
        const unsigned o3 = o2 + CS;

        const float u_zp = __ldg(P + o1 + SZ) - __ldg(T + o1 + SZ);
        const float u_zm = __ldg(P + o1 - SZ) - __ldg(T + o1 - SZ);
        const float u_yp = __ldg(P + o1 + SY) - __ldg(T + o1 + SY);
        const float u_ym = __ldg(P + o1 - SY) - __ldg(T + o1 - SY);
        const float v_zp = __ldg(P + o2 + SZ) - __ldg(T + o2 + SZ);
        const float v_zm = __ldg(P + o2 - SZ) - __ldg(T + o2 - SZ);
        const float v_xp = __ldg(P + o2 + 1u) - __ldg(T + o2 + 1u);
        const float v_xm = __ldg(P + o2 - 1u) - __ldg(T + o2 - 1u);
        const float w_yp = __ldg(P + o3 + SY) - __ldg(T + o3 + SY);
        const float w_ym = __ldg(P + o3 - SY) - __ldg(T + o3 - SY);
        const float w_xp = __ldg(P + o3 + 1u) - __ldg(T + o3 + 1u);
        const float w_xm = __ldg(P + o3 - 1u) - __ldg(T + o3 - 1u);

        const float vx = (w_yp - w_ym) - (v_zp - v_zm);
        const float vy = (u_zp - u_zm) - (w_xp - w_xm);
        const float vz = (v_xp - v_xm) - (u_yp - u_ym);

        lsum += sqrtf(vx * vx + vy * vy + vz * vz);
    }

    // ---- 5. Block reduce -> per-block partial slot + ticket ----
    #pragma unroll
    for (int off = 16; off; off >>= 1)
        lsum += __shfl_down_sync(0xFFFFFFFFu, lsum, off);
    if (lane == 0) wsum[warp] = lsum;
    __syncthreads();
    if (x == 0) {
        float ssum = 0.0f;
        #pragma unroll
        for (int i = 0; i < NW; ++i) ssum += wsum[i];
        g_part[bid] = (double)ssum;
        g_pcnt[bid] = total;
        __threadfence();
        const unsigned ticket = atomicAdd(&g_ctr, 1u);
        sIsLast = (ticket == NBLK - 1) ? 1 : 0;
    }
    __syncthreads();

    // ---- 6. Last block finalizes (and re-arms the ticket counter) ----
    if (sIsLast) {
        double ds = 0.0;
        long long dc = 0;
        for (int i = x; i < NBLK; i += NT) {
            ds += g_part[i];
            dc += (long long)g_pcnt[i];
        }
        #pragma unroll
        for (int off = 16; off; off >>= 1) {
            ds += __shfl_down_sync(0xFFFFFFFFu, ds, off);
            dc += __shfl_down_sync(0xFFFFFFFFu, dc, off);
        }
        __shared__ double fsum[NW];
        __shared__ long long fcnt[NW];
        if (lane == 0) { fsum[warp] = ds; fcnt[warp] = dc; }
        __syncthreads();
        if (x == 0) {
            double S = 0.0;
            long long C = 0;
            #pragma unroll
            for (int i = 0; i < NW; ++i) { S += fsum[i]; C += fcnt[i]; }
            out[0] = (float)(S / (double)C);
            g_ctr = 0u;   // re-arm for next graph replay
        }
    }
}

extern "C" void kernel_launch(void* const* d_in, const int* in_sizes, int n_in,
                              void* d_out, int out_size) {
    const float* P = (const float*)d_in[0];
    const float* T = (const float*)d_in[1];
    const float* M = (const float*)d_in[2];

    dim3 grid(32, 8, 2);
    dovn_fused_kernel<<<grid, NT>>>(P, T, M, (float*)d_out);
}